// round 6
// baseline (speedup 1.0000x reference)
#include <cuda_runtime.h>

// Problem constants
#define BATCH 8
#define IMH 180
#define IMW 180
#define NF 24
#define NB 31
#define NPIX (IMH * IMW)          // 32400
#define NTOT (BATCH * NPIX)       // 259200
#define N4   (NTOT / 4)           // 64800

#define TILE 32
#define UT 40                      // u tile (TILE + 2*4)
#define PT 36                      // phi tile (TILE + 2*2)

// LUT for phi(x) = sum_j w_j exp(-50 (x-mu_j)^2), x in [XMIN, XMAX]
#define NCELL 1024
#define XMIN (-2.0f)
#define XMAX (2.0f)
#define LUT_H ((XMAX - XMIN) / (float)NCELL)
#define LUT_INVH ((float)NCELL / (XMAX - XMIN))

#define NTHR 512                   // 4 filter-groups of 128 threads
#define NFG  6                     // filters per group

__device__ float  g_partials[64];
__device__ float2 g_lut[NCELL];

// ---------------------------------------------------------------------------
// k_init: blocks [0,4) build the 1024-cell LUT; blocks [4,68) compute
// weighted partial sums for M: sum(u_sigma)*9 = sum_p u[p]*cnt(p).
// ---------------------------------------------------------------------------
__global__ void k_init(const float* __restrict__ u,
                       const float* __restrict__ mu,
                       const float* __restrict__ wts) {
    const int tid = threadIdx.x;
    if (blockIdx.x < 4) {
        int i = blockIdx.x * 256 + tid;        // 0..1023
        float x0 = XMIN + (float)i * LUT_H;
        float x1 = x0 + LUT_H;
        float p0 = 0.f, p1 = 0.f;
        #pragma unroll 1
        for (int j = 0; j < NB; j++) {
            float m = mu[j], w = wts[j];
            float d0 = x0 - m, d1 = x1 - m;
            p0 += w * expf(-50.f * d0 * d0);
            p1 += w * expf(-50.f * d1 * d1);
        }
        g_lut[i] = make_float2(p0, p1 - p0);
    } else {
        __shared__ float sm[256];
        const int pb = blockIdx.x - 4;         // 0..63
        float s = 0.f;
        for (int i = pb * 256 + tid; i < N4; i += 64 * 256) {
            int idx4 = i * 4;
            int p = idx4 % NPIX;
            int y = p / IMW;
            int x0 = p - y * IMW;
            float wy = 3.f - (y == 0 ? 1.f : 0.f) - (y == IMH - 1 ? 1.f : 0.f);
            float4 v = ((const float4*)u)[i];
            float w0 = (x0 == 0) ? 2.f : 3.f;
            float w3 = (x0 == IMW - 4) ? 2.f : 3.f;
            s += wy * (v.x * w0 + v.y * 3.f + v.z * 3.f + v.w * w3);
        }
        sm[tid] = s;
        __syncthreads();
        for (int o = 128; o > 0; o >>= 1) {
            if (tid < o) sm[tid] += sm[tid + o];
            __syncthreads();
        }
        if (tid == 0) g_partials[pb] = sm[0];
    }
}

// ---------------------------------------------------------------------------
// k_main: fused TNRD stage per 32x32 tile; 4 filter-groups of 128 threads.
// Per group, per filter: forward(3x4 strips, ky-major) -> bar ->
// adjoint(2x4 strips, ky-major) -> bar. Taps are broadcast-LDS per ky row
// (only 5 live tap regs), keeping the body under the 64-reg cap.
// Dynamic smem layout (bytes):
//   [0, 8192)        sLUT  : 1024 x float2
//   [8192, 14592)    sU    : 40x40
//   [14592, 19776)   sUS   : 36x36 (u_sigma/M, zeroed outside image)
//   [19776, 40512)   sPhi  : 4 buffers of 36x36 (one per group)
//   [40512, 42912)   sF    : 24x25
// ---------------------------------------------------------------------------
#define OFF_LUT 0
#define OFF_U   8192
#define OFF_US  14592
#define OFF_PHI 19776
#define OFF_F   40512
#define PHI_STRIDE 5184
#define SMEM_BYTES 42912

__global__ __launch_bounds__(NTHR, 2) void k_main(
    const float* __restrict__ u,
    const float* __restrict__ f,
    const float* __restrict__ filt,
    const float* __restrict__ lam,
    float* __restrict__ out)
{
    extern __shared__ char smem[];
    float2* sLUT = (float2*)(smem + OFF_LUT);
    float*  sU   = (float*)(smem + OFF_U);
    float*  sUS  = (float*)(smem + OFF_US);
    float*  sF   = (float*)(smem + OFF_F);
    __shared__ float s_invM;

    const int b   = blockIdx.z;
    const int oy0 = blockIdx.y * TILE;
    const int ox0 = blockIdx.x * TILE;
    const int tid = threadIdx.x;
    const int g   = tid >> 7;          // filter-group 0..3
    const int gt  = tid & 127;         // lane within group

    const float* ub = u + b * NPIX;
    const float* fb = f + b * NPIX;
    float* ob = out + b * NPIX;

    float* sPhiG = (float*)(smem + OFF_PHI + g * PHI_STRIDE);

    // ---- invM: single-warp shuffle reduction over 64 partials ----
    if (tid < 32) {
        float s = g_partials[tid] + g_partials[tid + 32];
        #pragma unroll
        for (int o = 16; o > 0; o >>= 1)
            s += __shfl_down_sync(0xffffffffu, s, o);
        if (tid == 0)
            s_invM = 1.f / (s / (9.f * (float)NTOT) + 0.001f);
    }

    // ---- cooperative loads ----
    {
        const float4* lg = (const float4*)g_lut;
        float4* ls = (float4*)sLUT;
        ls[tid] = lg[tid];                         // 512 float4 = whole LUT
    }
    for (int i = tid; i < NF * 25; i += NTHR) sF[i] = filt[i];
    for (int i = tid; i < UT * UT; i += NTHR) {
        int r = i / UT, c = i - r * UT;
        int gy = oy0 - 4 + r, gx = ox0 - 4 + c;
        float v = 0.f;
        if ((unsigned)gy < IMH && (unsigned)gx < IMW) v = ub[gy * IMW + gx];
        sU[i] = v;
    }
    __syncthreads();

    const float invM = s_invM;

    // ---- u_sigma/M on phi tile; zero outside image ----
    for (int i = tid; i < PT * PT; i += NTHR) {
        int r = i / PT, c = i - r * PT;
        int gy = oy0 - 2 + r, gx = ox0 - 2 + c;
        float v = 0.f;
        if ((unsigned)gy < IMH && (unsigned)gx < IMW) {
            float s0 = sU[(r + 1) * UT + c + 1] + sU[(r + 1) * UT + c + 2] + sU[(r + 1) * UT + c + 3];
            float s1 = sU[(r + 2) * UT + c + 1] + sU[(r + 2) * UT + c + 2] + sU[(r + 2) * UT + c + 3];
            float s2 = sU[(r + 3) * UT + c + 1] + sU[(r + 3) * UT + c + 2] + sU[(r + 3) * UT + c + 3];
            v = (s0 + s1 + s2) * (1.f / 9.f) * invM;
        }
        sUS[i] = v;
    }
    __syncthreads();

    // ---- per-thread fixed strips ----
    // forward: 108 tasks of 3 rows x 4 cols over the 36x36 phi tile
    const int ffr0 = (gt / 9) * 3;
    const int ffc0 = (gt % 9) * 4;
    const bool fwd_on = (gt < 108);
    // adjoint: 128 tasks of 2 rows x 4 cols over the 32x32 output tile
    const int qr0 = (gt >> 3) * 2;
    const int qc0 = (gt & 7) * 4;

    float acc[8];
    #pragma unroll
    for (int k = 0; k < 8; k++) acc[k] = 0.f;

    const int fbase = g * NFG;

    #define GBAR() asm volatile("bar.sync %0, %1;" :: "r"(g + 1), "r"(128) : "memory")

    #pragma unroll 1
    for (int kf = 0; kf < NFG; kf++) {
        const float* Ff = &sF[(fbase + kf) * 25];

        // ---- forward: conv 5x5 (ky-major) + LUT phi + scale -> sPhiG ----
        if (fwd_on) {
            float a[12];
            #pragma unroll
            for (int k = 0; k < 12; k++) a[k] = 0.f;
            #pragma unroll
            for (int ky = 0; ky < 5; ky++) {
                float t0 = Ff[ky * 5 + 0], t1 = Ff[ky * 5 + 1], t2 = Ff[ky * 5 + 2];
                float t3 = Ff[ky * 5 + 3], t4 = Ff[ky * 5 + 4];
                #pragma unroll
                for (int rr = 0; rr < 3; rr++) {
                    const float4* rp = (const float4*)&sU[(ffr0 + rr + ky) * UT + ffc0];
                    float4 A = rp[0], B = rp[1];
                    float w0 = A.x, w1 = A.y, w2 = A.z, w3 = A.w;
                    float w4 = B.x, w5 = B.y, w6 = B.z, w7 = B.w;
                    a[rr*4+0] = fmaf(w0, t0, a[rr*4+0]); a[rr*4+1] = fmaf(w1, t0, a[rr*4+1]);
                    a[rr*4+2] = fmaf(w2, t0, a[rr*4+2]); a[rr*4+3] = fmaf(w3, t0, a[rr*4+3]);
                    a[rr*4+0] = fmaf(w1, t1, a[rr*4+0]); a[rr*4+1] = fmaf(w2, t1, a[rr*4+1]);
                    a[rr*4+2] = fmaf(w3, t1, a[rr*4+2]); a[rr*4+3] = fmaf(w4, t1, a[rr*4+3]);
                    a[rr*4+0] = fmaf(w2, t2, a[rr*4+0]); a[rr*4+1] = fmaf(w3, t2, a[rr*4+1]);
                    a[rr*4+2] = fmaf(w4, t2, a[rr*4+2]); a[rr*4+3] = fmaf(w5, t2, a[rr*4+3]);
                    a[rr*4+0] = fmaf(w3, t3, a[rr*4+0]); a[rr*4+1] = fmaf(w4, t3, a[rr*4+1]);
                    a[rr*4+2] = fmaf(w5, t3, a[rr*4+2]); a[rr*4+3] = fmaf(w6, t3, a[rr*4+3]);
                    a[rr*4+0] = fmaf(w4, t4, a[rr*4+0]); a[rr*4+1] = fmaf(w5, t4, a[rr*4+1]);
                    a[rr*4+2] = fmaf(w6, t4, a[rr*4+2]); a[rr*4+3] = fmaf(w7, t4, a[rr*4+3]);
                }
            }
            #pragma unroll
            for (int rr = 0; rr < 3; rr++) {
                float4 usv = *(const float4*)&sUS[(ffr0 + rr) * PT + ffc0];
                float us[4] = {usv.x, usv.y, usv.z, usv.w};
                float res[4];
                #pragma unroll
                for (int k = 0; k < 4; k++) {
                    float xc = fminf(fmaxf(a[rr * 4 + k], XMIN), XMAX);
                    float tt = (xc - XMIN) * LUT_INVH;
                    int ii = (int)tt;
                    ii = min(ii, NCELL - 1);
                    float frac = tt - (float)ii;
                    float2 cell = sLUT[ii];
                    res[k] = us[k] * fmaf(cell.y, frac, cell.x);
                }
                *(float4*)&sPhiG[(ffr0 + rr) * PT + ffc0] =
                    make_float4(res[0], res[1], res[2], res[3]);
            }
        }
        GBAR();

        // ---- adjoint: conv with flipped taps (ky-major) ----
        {
            float a[8];
            #pragma unroll
            for (int k = 0; k < 8; k++) a[k] = 0.f;
            #pragma unroll
            for (int ky = 0; ky < 5; ky++) {
                float t0 = Ff[(4 - ky) * 5 + 4], t1 = Ff[(4 - ky) * 5 + 3];
                float t2 = Ff[(4 - ky) * 5 + 2], t3 = Ff[(4 - ky) * 5 + 1];
                float t4 = Ff[(4 - ky) * 5 + 0];
                #pragma unroll
                for (int rr = 0; rr < 2; rr++) {
                    const float4* rp = (const float4*)&sPhiG[(qr0 + rr + ky) * PT + qc0];
                    float4 A = rp[0], B = rp[1];
                    float w0 = A.x, w1 = A.y, w2 = A.z, w3 = A.w;
                    float w4 = B.x, w5 = B.y, w6 = B.z, w7 = B.w;
                    a[rr*4+0] = fmaf(w0, t0, a[rr*4+0]); a[rr*4+1] = fmaf(w1, t0, a[rr*4+1]);
                    a[rr*4+2] = fmaf(w2, t0, a[rr*4+2]); a[rr*4+3] = fmaf(w3, t0, a[rr*4+3]);
                    a[rr*4+0] = fmaf(w1, t1, a[rr*4+0]); a[rr*4+1] = fmaf(w2, t1, a[rr*4+1]);
                    a[rr*4+2] = fmaf(w3, t1, a[rr*4+2]); a[rr*4+3] = fmaf(w4, t1, a[rr*4+3]);
                    a[rr*4+0] = fmaf(w2, t2, a[rr*4+0]); a[rr*4+1] = fmaf(w3, t2, a[rr*4+1]);
                    a[rr*4+2] = fmaf(w4, t2, a[rr*4+2]); a[rr*4+3] = fmaf(w5, t2, a[rr*4+3]);
                    a[rr*4+0] = fmaf(w3, t3, a[rr*4+0]); a[rr*4+1] = fmaf(w4, t3, a[rr*4+1]);
                    a[rr*4+2] = fmaf(w5, t3, a[rr*4+2]); a[rr*4+3] = fmaf(w6, t3, a[rr*4+3]);
                    a[rr*4+0] = fmaf(w4, t4, a[rr*4+0]); a[rr*4+1] = fmaf(w5, t4, a[rr*4+1]);
                    a[rr*4+2] = fmaf(w6, t4, a[rr*4+2]); a[rr*4+3] = fmaf(w7, t4, a[rr*4+3]);
                }
            }
            #pragma unroll
            for (int k = 0; k < 8; k++) acc[k] += a[k];
        }
        GBAR();
    }
    #undef GBAR

    // ---- combine group accumulators (groups 1..3 -> smem; group 0 sums) ----
    __syncthreads();                 // all groups done with their phi buffers
    if (g > 0) {
        float4* buf = (float4*)(smem + OFF_PHI + g * PHI_STRIDE);
        buf[gt * 2 + 0] = make_float4(acc[0], acc[1], acc[2], acc[3]);
        buf[gt * 2 + 1] = make_float4(acc[4], acc[5], acc[6], acc[7]);
    }
    __syncthreads();

    // ---- epilogue: reaction + clip (group 0) ----
    if (g == 0) {
        #pragma unroll
        for (int gg = 1; gg < 4; gg++) {
            const float4* buf = (const float4*)(smem + OFF_PHI + gg * PHI_STRIDE);
            float4 c0 = buf[gt * 2 + 0], c1 = buf[gt * 2 + 1];
            acc[0] += c0.x; acc[1] += c0.y; acc[2] += c0.z; acc[3] += c0.w;
            acc[4] += c1.x; acc[5] += c1.y; acc[6] += c1.z; acc[7] += c1.w;
        }
        const float lambda = lam[0];
        #pragma unroll
        for (int rr = 0; rr < 2; rr++) {
            const int gy = oy0 + qr0 + rr;
            if (gy < IMH) {
                float4 uv4 = *(const float4*)&sU[(qr0 + rr + 4) * UT + qc0 + 4];
                float uvs[4] = {uv4.x, uv4.y, uv4.z, uv4.w};
                #pragma unroll
                for (int k = 0; k < 4; k++) {
                    int gx = ox0 + qc0 + k;
                    if (gx < IMW) {
                        float uv = uvs[k];
                        float fv = fb[gy * IMW + gx];
                        float reac = lambda * (uv - fv) / (uv * uv + 1e-3f);
                        float o = uv - acc[rr * 4 + k] - reac;
                        o = fminf(fmaxf(o, 0.f), 1.f);
                        ob[gy * IMW + gx] = o;
                    }
                }
            }
        }
    }
}

// ---------------------------------------------------------------------------
// Launch
// ---------------------------------------------------------------------------
extern "C" void kernel_launch(void* const* d_in, const int* in_sizes, int n_in,
                              void* d_out, int out_size) {
    const float* u    = (const float*)d_in[0];
    const float* f    = (const float*)d_in[1];
    const float* filt = (const float*)d_in[2];
    const float* lam  = (const float*)d_in[3];
    const float* mu   = (const float*)d_in[4];
    const float* wts  = (const float*)d_in[5];
    float* out = (float*)d_out;

    k_init<<<68, 256>>>(u, mu, wts);
    dim3 grid((IMW + TILE - 1) / TILE, (IMH + TILE - 1) / TILE, BATCH);
    k_main<<<grid, NTHR, SMEM_BYTES>>>(u, f, filt, lam, out);
}